// round 13
// baseline (speedup 1.0000x reference)
#include <cuda_runtime.h>
#include <cuda_fp16.h>
#include <cstdint>

// Problem shape
#define B_M 2048
#define B_K 1024
#define B_N 4096

// GEMM tiling: CTA 128x128, 4 warps in 2x2, warp tile 64x64
#define TM 128
#define TN 128
#define KC 64                         // K per stage
#define KITERS (B_K / KC)             // 16
#define A_STAGE_BYTES (TM * KC * 2)   // 16 KB  (rows of 128B)
#define B_STAGE_BYTES (KC * TN * 2)   // 16 KB  (rows of 256B)
#define STAGE_BYTES (A_STAGE_BYTES + B_STAGE_BYTES)   // 32 KB
#define SMEM_WSQ_OFF (3 * STAGE_BYTES)
#define SMEM_BYTES (3 * STAGE_BYTES + TN * 4)   // 96.5 KB -> 2 CTAs/SM

#define WSEGS 32                      // W k-segments for deterministic partials

// ---------------------------------------------------------------------------
// Device scratch (allocation-free rule: __device__ globals)
// ---------------------------------------------------------------------------
__device__ __align__(16) __half g_xb[B_M * B_K];          // x fp16 [M,K]
__device__ __align__(16) __half g_wb[B_K * B_N];          // W fp16 [K,N]
__device__ float g_xsq[B_M];
__device__ float g_wpart[WSEGS * B_N];                    // deterministic partials

// ---------------------------------------------------------------------------
// PTX helpers (sm_80-era: accepted by the plain compute_103 PTX target)
// ---------------------------------------------------------------------------
__device__ __forceinline__ uint32_t smem_u32(const void* p) {
    uint32_t a;
    asm("{ .reg .u64 t; cvta.to.shared.u64 t, %1; cvt.u32.u64 %0, t; }"
        : "=r"(a) : "l"(p));
    return a;
}

__device__ __forceinline__ void cp_async16(uint32_t dst, const void* src) {
    asm volatile("cp.async.cg.shared.global [%0], [%1], 16;"
                 :: "r"(dst), "l"(src) : "memory");
}
#define CP_COMMIT() asm volatile("cp.async.commit_group;" ::: "memory")
#define CP_WAIT1()  asm volatile("cp.async.wait_group 1;" ::: "memory")

__device__ __forceinline__ void ldmatrix_x4(uint32_t* r, uint32_t addr) {
    asm volatile("ldmatrix.sync.aligned.m8n8.x4.shared.b16 {%0,%1,%2,%3}, [%4];"
                 : "=r"(r[0]), "=r"(r[1]), "=r"(r[2]), "=r"(r[3]) : "r"(addr));
}
__device__ __forceinline__ void ldmatrix_x4_trans(uint32_t* r, uint32_t addr) {
    asm volatile("ldmatrix.sync.aligned.m8n8.x4.trans.shared.b16 {%0,%1,%2,%3}, [%4];"
                 : "=r"(r[0]), "=r"(r[1]), "=r"(r[2]), "=r"(r[3]) : "r"(addr));
}

// f16 inputs, f32 accumulators
__device__ __forceinline__ void mma16816(float* c, const uint32_t* a, const uint32_t* b) {
    asm volatile(
        "mma.sync.aligned.m16n8k16.row.col.f32.f16.f16.f32 "
        "{%0,%1,%2,%3}, {%4,%5,%6,%7}, {%8,%9}, {%0,%1,%2,%3};"
        : "+f"(c[0]), "+f"(c[1]), "+f"(c[2]), "+f"(c[3])
        : "r"(a[0]), "r"(a[1]), "r"(a[2]), "r"(a[3]), "r"(b[0]), "r"(b[1]));
}

// ---------------------------------------------------------------------------
// Balanced prologue: 192 blocks x 256 threads, ~128KB I/O each.
// ---------------------------------------------------------------------------
__global__ void __launch_bounds__(256) k_prep(const float* __restrict__ x,
                                              const float* __restrict__ W) {
    const int tid = threadIdx.x;
    const int bid = blockIdx.x;
    const int wid = tid >> 5, lane = tid & 31;

    if (bid < 64) {
        #pragma unroll
        for (int rr = 0; rr < 4; rr++) {
            const int row = bid * 32 + wid * 4 + rr;
            float s = 0.f;
            #pragma unroll
            for (int j = 0; j < 8; j++) {
                const int c4 = lane + j * 32;
                float4 v = reinterpret_cast<const float4*>(x)[row * 256 + c4];
                s += v.x * v.x + v.y * v.y + v.z * v.z + v.w * v.w;
                __half2 lo = __floats2half2_rn(v.x, v.y);
                __half2 hi = __floats2half2_rn(v.z, v.w);
                uint2 p;
                p.x = *reinterpret_cast<uint32_t*>(&lo);
                p.y = *reinterpret_cast<uint32_t*>(&hi);
                reinterpret_cast<uint2*>(g_xb)[row * 256 + c4] = p;
            }
            #pragma unroll
            for (int o = 16; o; o >>= 1) s += __shfl_xor_sync(0xFFFFFFFFu, s, o);
            if (lane == 0) g_xsq[row] = s;
        }
    } else {
        const int wseg = bid - 64;                 // 0..127
        const int kseg = wseg >> 2;                // 0..31
        const int n4 = (wseg & 3) * 256 + tid;     // float4 column
        float4 acc = make_float4(0.f, 0.f, 0.f, 0.f);
        #pragma unroll 4
        for (int r = 0; r < 32; r++) {
            const int k = kseg * 32 + r;
            float4 v = reinterpret_cast<const float4*>(W)[(size_t)k * (B_N / 4) + n4];
            acc.x += v.x * v.x; acc.y += v.y * v.y;
            acc.z += v.z * v.z; acc.w += v.w * v.w;
            __half2 lo = __floats2half2_rn(v.x, v.y);
            __half2 hi = __floats2half2_rn(v.z, v.w);
            uint2 p;
            p.x = *reinterpret_cast<uint32_t*>(&lo);
            p.y = *reinterpret_cast<uint32_t*>(&hi);
            reinterpret_cast<uint2*>(g_wb)[(size_t)k * (B_N / 4) + n4] = p;
        }
        reinterpret_cast<float4*>(g_wpart)[kseg * (B_N / 4) + n4] = acc;
    }
}

// ---------------------------------------------------------------------------
// Main GEMM: mma.sync f16->f32, 3-stage cp.async, 2 CTAs/SM, CTA 128x128,
// warp tile 64x64, frag double-buffering, k-loop fully unrolled by 3
// (compile-time stage rotation), XOR-folded addressing, cross-barrier
// frag prefetch. 128 threads = 4 warps in 2(M) x 2(N).
// A smem: [128m x 64k], 128B rows, swizzle chunk^=(row&7)
// B smem: [64k x 128n], 256B rows, swizzle chunk^=(row&7)
// ---------------------------------------------------------------------------
template <int KS>
__device__ __forceinline__ void load_frags(uint32_t aB, uint32_t bB,
                                           uint32_t xbA, const uint32_t* xB,
                                           uint32_t a[4][4], uint32_t b[8][2]) {
    const uint32_t xa = xbA ^ (KS << 5);
    ldmatrix_x4(a[0], aB + xa);
    #pragma unroll
    for (int p = 0; p < 4; p++) {
        uint32_t t[4];
        ldmatrix_x4_trans(t, bB + KS * 4096 + xB[p]);
        b[2 * p + 0][0] = t[0]; b[2 * p + 0][1] = t[1];
        b[2 * p + 1][0] = t[2]; b[2 * p + 1][1] = t[3];
    }
    ldmatrix_x4(a[1], aB + 2048 + xa);
    ldmatrix_x4(a[2], aB + 4096 + xa);
    ldmatrix_x4(a[3], aB + 6144 + xa);
}

#define MMAS(AF, BF) do { \
    _Pragma("unroll") \
    for (int mt = 0; mt < 4; mt++) \
        _Pragma("unroll") \
        for (int nt = 0; nt < 8; nt++) \
            mma16816(acc[mt][nt], (AF)[mt], (BF)[nt]); \
} while (0)

__global__ void __launch_bounds__(128, 2)
k_euclid_gemm(float* __restrict__ out) {
    extern __shared__ uint8_t dsmem[];
    const int tid = threadIdx.x;
    const int wid = tid >> 5, lane = tid & 31;
    const int mw = wid & 1, nw = wid >> 1;        // 2 x 2 warp grid
    const int m_base = blockIdx.x * TM;
    const int n_base = blockIdx.y * TN;

    const uint32_t sbase = smem_u32(dsmem);
    float* wsq_s = reinterpret_cast<float*>(dsmem + SMEM_WSQ_OFF);

    // Fold the wsq reduction into this CTA: 128 threads x 32 partials.
    {
        float t = 0.f;
        #pragma unroll
        for (int i = 0; i < WSEGS; i++) t += g_wpart[i * B_N + n_base + tid];
        wsq_s[tid] = t;
    }

    // ---- precomputed addressing ----
    const int hi = lane >> 4;
    const int l15 = lane & 15;
    const int lsw = lane & 7;
    const uint32_t xbA = (uint32_t)((hi ^ lsw) << 4);     // xA(ks) = xbA ^ (ks<<5)
    uint32_t xB[4];
    #pragma unroll
    for (int p = 0; p < 4; p++)
        xB[p] = (uint32_t)(((nw * 8 + p * 2 + hi) ^ lsw) << 4);
    const uint32_t arow = (uint32_t)((mw * 64 + l15) * 128);
    const uint32_t brow = (uint32_t)(l15 * 256);

    // cp.async bases (A: 8 chunks/row of 128B; B: 16 chunks/row of 256B)
    const int r0a = tid >> 3, c0a = tid & 7;
    const uint32_t dstA = (uint32_t)(r0a * 128 + ((c0a ^ (r0a & 7)) << 4));
    const char* pA = reinterpret_cast<const char*>(g_xb)
                     + ((size_t)(m_base + r0a) * B_K + c0a * 8) * 2;
    const int r0b = tid >> 4, c0b = tid & 15;
    const uint32_t dstB = (uint32_t)(r0b * 256 + ((c0b ^ (r0b & 7)) << 4));
    const char* pB = reinterpret_cast<const char*>(g_wb)
                     + ((size_t)r0b * B_N + n_base + c0b * 8) * 2;

#define LDGSTS_A(T_) do { \
        _Pragma("unroll") \
        for (int j = 0; j < 8; j++) \
            cp_async16((T_) + dstA + j * 2048, pA + (size_t)j * (16 * B_K * 2)); \
    } while (0)
#define LDGSTS_B(T_) do { \
        _Pragma("unroll") \
        for (int j = 0; j < 8; j++) \
            cp_async16((T_) + A_STAGE_BYTES + dstB + j * 2048, \
                       pB + (size_t)j * (8 * B_N * 2)); \
    } while (0)

    float acc[4][8][4];                           // fp32 accumulators (128 regs)
    #pragma unroll
    for (int i = 0; i < 4; i++)
        #pragma unroll
        for (int j = 0; j < 8; j++)
            #pragma unroll
            for (int e = 0; e < 4; e++) acc[i][j][e] = 0.f;

    // prefetch stages 0, 1
    LDGSTS_A(sbase); LDGSTS_B(sbase); CP_COMMIT();
    pA += KC * 2; pB += (size_t)KC * B_N * 2;
    LDGSTS_A(sbase + STAGE_BYTES); LDGSTS_B(sbase + STAGE_BYTES); CP_COMMIT();
    pA += KC * 2; pB += (size_t)KC * B_N * 2;     // now at chunk 2

    CP_WAIT1();                                   // stage 0 complete
    __syncthreads();

    uint32_t a0[4][4], b0[8][2];                  // frag double buffers (64 regs)
    uint32_t a1[4][4], b1[8][2];
    load_frags<0>(sbase + arow, sbase + A_STAGE_BYTES + brow, xbA, xB, a0, b0);

    // KBODY: compute stage TC, next stage TN_, load gmem into TL.
    // Entering: frags (k, ks0) in a0/b0. Exits with (k+1, ks0) in a0/b0.
#define KBODY(TC_, TN_, TL_, M2_, M1_) do {                                    \
        const uint32_t tC = sbase + (TC_);                                     \
        const uint32_t aB_ = tC + arow, bB_ = tC + A_STAGE_BYTES + brow;       \
        /* ks0 */                                                              \
        load_frags<1>(aB_, bB_, xbA, xB, a1, b1);                              \
        MMAS(a0, b0);                                                          \
        if (M2_) LDGSTS_A(sbase + (TL_));                                      \
        /* ks1 */                                                              \
        load_frags<2>(aB_, bB_, xbA, xB, a0, b0);                              \
        MMAS(a1, b1);                                                          \
        if (M2_) {                                                             \
            LDGSTS_B(sbase + (TL_));                                           \
            pA += KC * 2; pB += (size_t)KC * B_N * 2;                          \
        }                                                                      \
        CP_COMMIT();                                                           \
        /* ks2 */                                                              \
        load_frags<3>(aB_, bB_, xbA, xB, a1, b1);                              \
        MMAS(a0, b0);                                                          \
        /* ks3: wait stage k+1 + barrier, prefetch its ks0 frags, mma */       \
        CP_WAIT1();                                                            \
        __syncthreads();                                                       \
        if (M1_)                                                               \
            load_frags<0>(sbase + (TN_) + arow,                                \
                          sbase + (TN_) + A_STAGE_BYTES + brow,                \
                          xbA, xB, a0, b0);                                    \
        MMAS(a1, b1);                                                          \
    } while (0)

    #pragma unroll 1
    for (int kk = 0; kk < 4; kk++) {              // k = 0..11
        KBODY(0,              STAGE_BYTES,     2 * STAGE_BYTES, true, true);
        KBODY(STAGE_BYTES,    2 * STAGE_BYTES, 0,               true, true);
        KBODY(2 * STAGE_BYTES, 0,              STAGE_BYTES,     true, true);
    }
    KBODY(0,              STAGE_BYTES,     2 * STAGE_BYTES, true,  true);  // k=12
    KBODY(STAGE_BYTES,    2 * STAGE_BYTES, 0,               true,  true);  // k=13
    KBODY(2 * STAGE_BYTES, 0,              STAGE_BYTES,     false, true);  // k=14
    KBODY(0,              STAGE_BYTES,     2 * STAGE_BYTES, false, false); // k=15
#undef KBODY
#undef LDGSTS_A
#undef LDGSTS_B

    // Epilogue: out[m,n] = acc - 0.5*(xsq[m] + wsq[n])
    #pragma unroll
    for (int mt = 0; mt < 4; mt++) {
        const int r = m_base + mw * 64 + mt * 16 + (lane >> 2);
        const float xs0 = g_xsq[r];
        const float xs1 = g_xsq[r + 8];
        #pragma unroll
        for (int nt = 0; nt < 8; nt++) {
            const int nl = nw * 64 + nt * 8 + (lane & 3) * 2;
            const float2 ws = *reinterpret_cast<const float2*>(&wsq_s[nl]);
            const int n = n_base + nl;
            float2 o0, o1;
            o0.x = acc[mt][nt][0] - 0.5f * (xs0 + ws.x);
            o0.y = acc[mt][nt][1] - 0.5f * (xs0 + ws.y);
            o1.x = acc[mt][nt][2] - 0.5f * (xs1 + ws.x);
            o1.y = acc[mt][nt][3] - 0.5f * (xs1 + ws.y);
            *reinterpret_cast<float2*>(&out[(size_t)r * B_N + n]) = o0;
            *reinterpret_cast<float2*>(&out[(size_t)(r + 8) * B_N + n]) = o1;
        }
    }
}

// ---------------------------------------------------------------------------
// Launch
// ---------------------------------------------------------------------------
extern "C" void kernel_launch(void* const* d_in, const int* in_sizes, int n_in,
                              void* d_out, int out_size) {
    const float* x = (const float*)d_in[0];   // [2048, 1024]
    const float* W = (const float*)d_in[1];   // [1024, 4096]
    float* out = (float*)d_out;               // [2048, 4096]

    k_prep<<<192, 256>>>(x, W);

    cudaFuncSetAttribute(k_euclid_gemm,
                         cudaFuncAttributeMaxDynamicSharedMemorySize, SMEM_BYTES);
    k_euclid_gemm<<<dim3(B_M / TM, B_N / TN), 128, SMEM_BYTES>>>(out);
}

// round 14
// speedup vs baseline: 1.0833x; 1.0833x over previous
#include <cuda_runtime.h>
#include <cuda_fp16.h>
#include <cstdint>

// Problem shape
#define B_M 2048
#define B_K 1024
#define B_N 4096

// GEMM tiling: CTA 128x64, 4 warps in 2x2, warp tile 64x32
#define TM 128
#define TN 64
#define KC 64                         // K per stage
#define KITERS (B_K / KC)             // 16
#define A_STAGE_BYTES (TM * KC * 2)   // 16 KB  (rows of 128B)
#define B_STAGE_BYTES (KC * TN * 2)   // 8 KB   (rows of 128B)
#define STAGE_BYTES (A_STAGE_BYTES + B_STAGE_BYTES)   // 24 KB
#define SMEM_WSQ_OFF (3 * STAGE_BYTES)
#define SMEM_BYTES (3 * STAGE_BYTES + TN * 4)   // 72.25 KB -> 3 CTAs/SM

#define WSEGS 32                      // W k-segments for deterministic partials

// ---------------------------------------------------------------------------
// Device scratch (allocation-free rule: __device__ globals)
// ---------------------------------------------------------------------------
__device__ __align__(16) __half g_xb[B_M * B_K];          // x fp16 [M,K]
__device__ __align__(16) __half g_wb[B_K * B_N];          // W fp16 [K,N]
__device__ float g_xsq[B_M];
__device__ float g_wpart[WSEGS * B_N];                    // deterministic partials

// ---------------------------------------------------------------------------
// PTX helpers (sm_80-era: accepted by the plain compute_103 PTX target)
// ---------------------------------------------------------------------------
__device__ __forceinline__ uint32_t smem_u32(const void* p) {
    uint32_t a;
    asm("{ .reg .u64 t; cvta.to.shared.u64 t, %1; cvt.u32.u64 %0, t; }"
        : "=r"(a) : "l"(p));
    return a;
}

__device__ __forceinline__ void cp_async16(uint32_t dst, const void* src) {
    asm volatile("cp.async.cg.shared.global [%0], [%1], 16;"
                 :: "r"(dst), "l"(src) : "memory");
}
#define CP_COMMIT() asm volatile("cp.async.commit_group;" ::: "memory")
#define CP_WAIT1()  asm volatile("cp.async.wait_group 1;" ::: "memory")

__device__ __forceinline__ void ldmatrix_x4(uint32_t* r, uint32_t addr) {
    asm volatile("ldmatrix.sync.aligned.m8n8.x4.shared.b16 {%0,%1,%2,%3}, [%4];"
                 : "=r"(r[0]), "=r"(r[1]), "=r"(r[2]), "=r"(r[3]) : "r"(addr));
}
__device__ __forceinline__ void ldmatrix_x4_trans(uint32_t* r, uint32_t addr) {
    asm volatile("ldmatrix.sync.aligned.m8n8.x4.trans.shared.b16 {%0,%1,%2,%3}, [%4];"
                 : "=r"(r[0]), "=r"(r[1]), "=r"(r[2]), "=r"(r[3]) : "r"(addr));
}

// f16 inputs, f32 accumulators
__device__ __forceinline__ void mma16816(float* c, const uint32_t* a, const uint32_t* b) {
    asm volatile(
        "mma.sync.aligned.m16n8k16.row.col.f32.f16.f16.f32 "
        "{%0,%1,%2,%3}, {%4,%5,%6,%7}, {%8,%9}, {%0,%1,%2,%3};"
        : "+f"(c[0]), "+f"(c[1]), "+f"(c[2]), "+f"(c[3])
        : "r"(a[0]), "r"(a[1]), "r"(a[2]), "r"(a[3]), "r"(b[0]), "r"(b[1]));
}

// ---------------------------------------------------------------------------
// Balanced prologue: 192 blocks x 256 threads, ~128KB I/O each.
// ---------------------------------------------------------------------------
__global__ void __launch_bounds__(256) k_prep(const float* __restrict__ x,
                                              const float* __restrict__ W) {
    const int tid = threadIdx.x;
    const int bid = blockIdx.x;
    const int wid = tid >> 5, lane = tid & 31;

    if (bid < 64) {
        #pragma unroll
        for (int rr = 0; rr < 4; rr++) {
            const int row = bid * 32 + wid * 4 + rr;
            float s = 0.f;
            #pragma unroll
            for (int j = 0; j < 8; j++) {
                const int c4 = lane + j * 32;
                float4 v = reinterpret_cast<const float4*>(x)[row * 256 + c4];
                s += v.x * v.x + v.y * v.y + v.z * v.z + v.w * v.w;
                __half2 lo = __floats2half2_rn(v.x, v.y);
                __half2 hi = __floats2half2_rn(v.z, v.w);
                uint2 p;
                p.x = *reinterpret_cast<uint32_t*>(&lo);
                p.y = *reinterpret_cast<uint32_t*>(&hi);
                reinterpret_cast<uint2*>(g_xb)[row * 256 + c4] = p;
            }
            #pragma unroll
            for (int o = 16; o; o >>= 1) s += __shfl_xor_sync(0xFFFFFFFFu, s, o);
            if (lane == 0) g_xsq[row] = s;
        }
    } else {
        const int wseg = bid - 64;                 // 0..127
        const int kseg = wseg >> 2;                // 0..31
        const int n4 = (wseg & 3) * 256 + tid;     // float4 column
        float4 acc = make_float4(0.f, 0.f, 0.f, 0.f);
        #pragma unroll 4
        for (int r = 0; r < 32; r++) {
            const int k = kseg * 32 + r;
            float4 v = reinterpret_cast<const float4*>(W)[(size_t)k * (B_N / 4) + n4];
            acc.x += v.x * v.x; acc.y += v.y * v.y;
            acc.z += v.z * v.z; acc.w += v.w * v.w;
            __half2 lo = __floats2half2_rn(v.x, v.y);
            __half2 hi = __floats2half2_rn(v.z, v.w);
            uint2 p;
            p.x = *reinterpret_cast<uint32_t*>(&lo);
            p.y = *reinterpret_cast<uint32_t*>(&hi);
            reinterpret_cast<uint2*>(g_wb)[(size_t)k * (B_N / 4) + n4] = p;
        }
        reinterpret_cast<float4*>(g_wpart)[kseg * (B_N / 4) + n4] = acc;
    }
}

// ---------------------------------------------------------------------------
// Main GEMM: mma.sync f16->f32, 3-stage cp.async (wait_group 1), 3 CTAs/SM,
// CTA 128x64, warp tile 64x32, frag double-buffering, k-loop unrolled by 3
// (compile-time stage rotation), XOR-folded addressing, cross-barrier
// frag prefetch. 128 threads = 4 warps in 2(M) x 2(N).
// A smem: [128m x 64k], 128B rows; B smem: [64k x 64n], 128B rows.
// ---------------------------------------------------------------------------
template <int KS>
__device__ __forceinline__ void load_frags(uint32_t aB, uint32_t bB,
                                           uint32_t xbA, const uint32_t* xB,
                                           uint32_t a[4][4], uint32_t b[4][2]) {
    const uint32_t xa = xbA ^ (KS << 5);
    ldmatrix_x4(a[0], aB + xa);
    uint32_t t0[4], t1[4];
    ldmatrix_x4_trans(t0, bB + KS * 2048 + xB[0]);
    ldmatrix_x4_trans(t1, bB + KS * 2048 + xB[1]);
    ldmatrix_x4(a[1], aB + 2048 + xa);
    ldmatrix_x4(a[2], aB + 4096 + xa);
    ldmatrix_x4(a[3], aB + 6144 + xa);
    b[0][0] = t0[0]; b[0][1] = t0[1];
    b[1][0] = t0[2]; b[1][1] = t0[3];
    b[2][0] = t1[0]; b[2][1] = t1[1];
    b[3][0] = t1[2]; b[3][1] = t1[3];
}

#define MMAS(AF, BF) do { \
    _Pragma("unroll") \
    for (int mt = 0; mt < 4; mt++) \
        _Pragma("unroll") \
        for (int nt = 0; nt < 4; nt++) \
            mma16816(acc[mt][nt], (AF)[mt], (BF)[nt]); \
} while (0)

__global__ void __launch_bounds__(128, 3)
k_euclid_gemm(float* __restrict__ out) {
    extern __shared__ uint8_t dsmem[];
    const int tid = threadIdx.x;
    const int wid = tid >> 5, lane = tid & 31;
    const int mw = wid & 1, nw = wid >> 1;        // 2 x 2 warp grid
    const int m_base = blockIdx.x * TM;
    const int n_base = blockIdx.y * TN;

    const uint32_t sbase = smem_u32(dsmem);
    float* wsq_s = reinterpret_cast<float*>(dsmem + SMEM_WSQ_OFF);

    // Fold the wsq reduction into this CTA: 64 threads x 32 partials.
    if (tid < TN) {
        float t = 0.f;
        #pragma unroll
        for (int i = 0; i < WSEGS; i++) t += g_wpart[i * B_N + n_base + tid];
        wsq_s[tid] = t;
    }

    // ---- precomputed addressing ----
    const int hi = lane >> 4;
    const int l15 = lane & 15;
    const int lsw = lane & 7;
    const uint32_t xbA = (uint32_t)((hi ^ lsw) << 4);     // xA(ks) = xbA ^ (ks<<5)
    uint32_t xB[2];
    #pragma unroll
    for (int p = 0; p < 2; p++)
        xB[p] = (uint32_t)(((nw * 4 + p * 2 + hi) ^ lsw) << 4);
    const uint32_t arow = (uint32_t)((mw * 64 + l15) * 128);
    const uint32_t brow = (uint32_t)(l15 * 128);

    // cp.async bases (A and B both: 8 chunks per 128B row)
    const int r0 = tid >> 3, c0 = tid & 7;
    const uint32_t dst0 = (uint32_t)(r0 * 128 + ((c0 ^ (r0 & 7)) << 4));
    const char* pA = reinterpret_cast<const char*>(g_xb)
                     + ((size_t)(m_base + r0) * B_K + c0 * 8) * 2;
    const char* pB = reinterpret_cast<const char*>(g_wb)
                     + ((size_t)r0 * B_N + n_base + c0 * 8) * 2;

#define LDGSTS_A(T_) do { \
        _Pragma("unroll") \
        for (int j = 0; j < 8; j++) \
            cp_async16((T_) + dst0 + j * 2048, pA + (size_t)j * (16 * B_K * 2)); \
    } while (0)
#define LDGSTS_B(T_) do { \
        _Pragma("unroll") \
        for (int j = 0; j < 4; j++) \
            cp_async16((T_) + A_STAGE_BYTES + dst0 + j * 2048, \
                       pB + (size_t)j * (16 * B_N * 2)); \
    } while (0)

    float acc[4][4][4];                           // fp32 accumulators (64 regs)
    #pragma unroll
    for (int i = 0; i < 4; i++)
        #pragma unroll
        for (int j = 0; j < 4; j++)
            #pragma unroll
            for (int e = 0; e < 4; e++) acc[i][j][e] = 0.f;

    // prefetch stages 0, 1
    LDGSTS_A(sbase); LDGSTS_B(sbase); CP_COMMIT();
    pA += KC * 2; pB += (size_t)KC * B_N * 2;
    LDGSTS_A(sbase + STAGE_BYTES); LDGSTS_B(sbase + STAGE_BYTES); CP_COMMIT();
    pA += KC * 2; pB += (size_t)KC * B_N * 2;     // now at chunk 2

    CP_WAIT1();                                   // stage 0 complete
    __syncthreads();

    uint32_t a0[4][4], b0[4][2];                  // frag double buffers (48 regs)
    uint32_t a1[4][4], b1[4][2];
    load_frags<0>(sbase + arow, sbase + A_STAGE_BYTES + brow, xbA, xB, a0, b0);

    // KBODY: compute stage TC_, next stage TN_, gmem-load into slot TL_.
    // Entering: frags (k, ks0) in a0/b0. Exits with (k+1, ks0) in a0/b0.
#define KBODY(TC_, TN_, TL_, M2_, M1_) do {                                    \
        const uint32_t tC = sbase + (TC_);                                     \
        const uint32_t aB_ = tC + arow, bB_ = tC + A_STAGE_BYTES + brow;       \
        /* ks0 */                                                              \
        load_frags<1>(aB_, bB_, xbA, xB, a1, b1);                              \
        MMAS(a0, b0);                                                          \
        if (M2_) LDGSTS_A(sbase + (TL_));                                      \
        /* ks1 */                                                              \
        load_frags<2>(aB_, bB_, xbA, xB, a0, b0);                              \
        MMAS(a1, b1);                                                          \
        if (M2_) {                                                             \
            LDGSTS_B(sbase + (TL_));                                           \
            pA += KC * 2; pB += (size_t)KC * B_N * 2;                          \
        }                                                                      \
        CP_COMMIT();                                                           \
        /* ks2 */                                                              \
        load_frags<3>(aB_, bB_, xbA, xB, a1, b1);                              \
        MMAS(a0, b0);                                                          \
        /* ks3: wait stage k+1 + barrier, prefetch its ks0 frags, mma */       \
        CP_WAIT1();                                                            \
        __syncthreads();                                                       \
        if (M1_)                                                               \
            load_frags<0>(sbase + (TN_) + arow,                                \
                          sbase + (TN_) + A_STAGE_BYTES + brow,                \
                          xbA, xB, a0, b0);                                    \
        MMAS(a1, b1);                                                          \
    } while (0)

    #pragma unroll 1
    for (int kk = 0; kk < 4; kk++) {              // k = 0..11
        KBODY(0,               STAGE_BYTES,     2 * STAGE_BYTES, true, true);
        KBODY(STAGE_BYTES,     2 * STAGE_BYTES, 0,               true, true);
        KBODY(2 * STAGE_BYTES, 0,               STAGE_BYTES,     true, true);
    }
    KBODY(0,               STAGE_BYTES,     2 * STAGE_BYTES, true,  true);  // k=12
    KBODY(STAGE_BYTES,     2 * STAGE_BYTES, 0,               true,  true);  // k=13
    KBODY(2 * STAGE_BYTES, 0,               STAGE_BYTES,     false, true);  // k=14
    KBODY(0,               STAGE_BYTES,     2 * STAGE_BYTES, false, false); // k=15
#undef KBODY
#undef LDGSTS_A
#undef LDGSTS_B

    // Epilogue: out[m,n] = acc - 0.5*(xsq[m] + wsq[n])
    #pragma unroll
    for (int mt = 0; mt < 4; mt++) {
        const int r = m_base + mw * 64 + mt * 16 + (lane >> 2);
        const float xs0 = g_xsq[r];
        const float xs1 = g_xsq[r + 8];
        #pragma unroll
        for (int nt = 0; nt < 4; nt++) {
            const int nl = nw * 32 + nt * 8 + (lane & 3) * 2;
            const float2 ws = *reinterpret_cast<const float2*>(&wsq_s[nl]);
            const int n = n_base + nl;
            float2 o0, o1;
            o0.x = acc[mt][nt][0] - 0.5f * (xs0 + ws.x);
            o0.y = acc[mt][nt][1] - 0.5f * (xs0 + ws.y);
            o1.x = acc[mt][nt][2] - 0.5f * (xs1 + ws.x);
            o1.y = acc[mt][nt][3] - 0.5f * (xs1 + ws.y);
            *reinterpret_cast<float2*>(&out[(size_t)r * B_N + n]) = o0;
            *reinterpret_cast<float2*>(&out[(size_t)(r + 8) * B_N + n]) = o1;
        }
    }
}

// ---------------------------------------------------------------------------
// Launch
// ---------------------------------------------------------------------------
extern "C" void kernel_launch(void* const* d_in, const int* in_sizes, int n_in,
                              void* d_out, int out_size) {
    const float* x = (const float*)d_in[0];   // [2048, 1024]
    const float* W = (const float*)d_in[1];   // [1024, 4096]
    float* out = (float*)d_out;               // [2048, 4096]

    k_prep<<<192, 256>>>(x, W);

    cudaFuncSetAttribute(k_euclid_gemm,
                         cudaFuncAttributeMaxDynamicSharedMemorySize, SMEM_BYTES);
    k_euclid_gemm<<<dim3(B_M / TM, B_N / TN), 128, SMEM_BYTES>>>(out);
}